// round 15
// baseline (speedup 1.0000x reference)
#include <cuda_runtime.h>
#include <cooperative_groups.h>
#include <cstdint>

namespace cg = cooperative_groups;

// ---------------- problem dims ----------------
#define BB 512
#define TT 64
#define HH 256     // hidden / obs dim
#define AA 6       // action dim
#define RR 256     // recurrent dim
#define KG 768     // 3*RR gate dim
#define LL 1024    // latent dim
#define NCTA 128   // scan CTAs (64 clusters of 2); each cluster owns 8 rows, each CTA owns 4

// output layout: [deter | stoch | logits]
#define DET_OFF 0
#define ST_OFF  (BB * TT * RR)
#define LG_OFF  (BB * TT * RR + BB * TT * LL)

// ---------------- device scratch ----------------
__device__ __align__(16) float g_WcT[LL * KG];     // [c][k] fused stoch weights
__device__ __align__(16) float g_WcaT[AA * KG];    // [j][k] fused action weights
__device__ __align__(16) float g_bc[KG];           // b_ih + W_ih @ b_in
__device__ __align__(16) float g_WhhT[RR * KG];    // [j][k]
__device__ __align__(16) float g_WphT[RR * LL];    // [j][l]
__device__ __align__(16) float g_WpoT[HH * LL];    // [k][n]
__device__ int g_cnt[TT];                          // per-slice obs-logits ready counters

// ---------------- packed fp32 helpers (FFMA2 path) ----------------
__device__ __forceinline__ void ffma2(float2& d, const float2 a, const float2 b) {
    asm("fma.rn.f32x2 %0, %1, %2, %0;"
        : "+l"(reinterpret_cast<unsigned long long&>(d))
        : "l"(reinterpret_cast<const unsigned long long&>(a)),
          "l"(reinterpret_cast<const unsigned long long&>(b)));
}

// ---------------- prep 1: fused GEMM  C[c][k] = sum_h W_in[h][c] * W_ih[k][h] ----------------
__global__ void __launch_bounds__(256) prep_fuse(const float* __restrict__ W_in,
                                                 const float* __restrict__ b_in,
                                                 const float* __restrict__ W_ih,
                                                 const float* __restrict__ b_ih) {
    __shared__ float As[16][64 + 1];
    __shared__ float Bs[16][64 + 1];
    const int tid = threadIdx.x;
    const int bk = blockIdx.x * 64;
    const int bc = blockIdx.y * 64;
    const int tyc = tid >> 4;
    const int txk = tid & 15;

    float acc[4][4];
    #pragma unroll
    for (int i = 0; i < 4; ++i)
        #pragma unroll
        for (int j = 0; j < 4; ++j) acc[i][j] = 0.f;

    for (int k0 = 0; k0 < HH; k0 += 16) {
        #pragma unroll
        for (int i = 0; i < 4; ++i) {
            int e = tid + i * 256;
            int kk = e >> 6, cc = e & 63;
            int c = bc + cc;
            float v = 0.f;
            if (c < 1030)       v = W_in[(size_t)(k0 + kk) * 1030 + c];
            else if (c == 1030) v = b_in[k0 + kk];
            As[kk][cc] = v;
        }
        #pragma unroll
        for (int i = 0; i < 4; ++i) {
            int e = tid + i * 256;
            int kn = e >> 4, kk = e & 15;
            Bs[kk][kn] = W_ih[(size_t)(bk + kn) * HH + k0 + kk];
        }
        __syncthreads();
        #pragma unroll
        for (int kk = 0; kk < 16; ++kk) {
            float a[4], b[4];
            #pragma unroll
            for (int i = 0; i < 4; ++i) a[i] = As[kk][tyc * 4 + i];
            #pragma unroll
            for (int j = 0; j < 4; ++j) b[j] = Bs[kk][txk * 4 + j];
            #pragma unroll
            for (int i = 0; i < 4; ++i)
                #pragma unroll
                for (int j = 0; j < 4; ++j)
                    acc[i][j] = fmaf(a[i], b[j], acc[i][j]);
        }
        __syncthreads();
    }
    #pragma unroll
    for (int i = 0; i < 4; ++i) {
        int c = bc + tyc * 4 + i;
        int k = bk + txk * 4;
        if (c < LL) {
            *(float4*)&g_WcT[(size_t)c * KG + k] =
                make_float4(acc[i][0], acc[i][1], acc[i][2], acc[i][3]);
        } else if (c < 1030) {
            *(float4*)&g_WcaT[(size_t)(c - LL) * KG + k] =
                make_float4(acc[i][0], acc[i][1], acc[i][2], acc[i][3]);
        } else if (c == 1030) {
            float4 bi = *(const float4*)&b_ih[k];
            g_bc[k + 0] = acc[i][0] + bi.x;
            g_bc[k + 1] = acc[i][1] + bi.y;
            g_bc[k + 2] = acc[i][2] + bi.z;
            g_bc[k + 3] = acc[i][3] + bi.w;
        }
    }
}

// ---------------- prep 2: tiled transposes ----------------
__global__ void __launch_bounds__(256) prep_transpose(const float* __restrict__ W_hh,
                                                      const float* __restrict__ W_post) {
    __shared__ float tile[32][33];
    const int tid = threadIdx.x;
    const int tx = tid & 31;
    const int ty0 = tid >> 5;
    const int z = blockIdx.z;
    const int row0 = blockIdx.x * 32;
    const int col0 = blockIdx.y * 32;

    if (z == 0) {
        if (blockIdx.x >= 24 || blockIdx.y >= 8) return;
        #pragma unroll
        for (int r = 0; r < 4; ++r) {
            int row = ty0 + r * 8;
            tile[row][tx] = W_hh[(size_t)(row0 + row) * RR + col0 + tx];
        }
        __syncthreads();
        #pragma unroll
        for (int r = 0; r < 4; ++r) {
            int row = ty0 + r * 8;
            g_WhhT[(size_t)(col0 + row) * KG + row0 + tx] = tile[tx][row];
        }
    } else {
        #pragma unroll
        for (int r = 0; r < 4; ++r) {
            int row = ty0 + r * 8;
            tile[row][tx] = W_post[(size_t)(row0 + row) * (RR + HH) + col0 + tx];
        }
        __syncthreads();
        #pragma unroll
        for (int r = 0; r < 4; ++r) {
            int row = ty0 + r * 8;
            int m = col0 + row;
            float v = tile[tx][row];
            if (m < RR) g_WphT[(size_t)m * LL + row0 + tx] = v;
            else        g_WpoT[(size_t)(m - RR) * LL + row0 + tx] = v;
        }
    }
}

// ---------------- fallback obs GEMM (used only if device has <130 SMs) ----------------
__global__ void __launch_bounds__(256) obs_gemm(const float* __restrict__ obs,
                                                const float* __restrict__ b_post,
                                                float* __restrict__ outL) {
    __shared__ float2 As2[128][17];
    __shared__ float  Bs[16][64];
    const int tid = threadIdx.x;
    const int bm = blockIdx.y * 128;
    const int bn = blockIdx.x * 64;
    const int ty = tid >> 4;
    const int tx = tid & 15;
    float2 acc2[8][2];
    #pragma unroll
    for (int i = 0; i < 8; ++i) { acc2[i][0] = make_float2(0.f, 0.f); acc2[i][1] = make_float2(0.f, 0.f); }

    for (int k0 = 0; k0 < HH; k0 += 16) {
        #pragma unroll
        for (int i = 0; i < 2; ++i) {
            int f = tid + i * 256;
            int row = f >> 2;
            int kp = (f & 3) * 4;
            float4 v = *(const float4*)&obs[(size_t)(bm + row) * HH + k0 + kp];
            As2[row][kp + 0] = make_float2(v.x, v.x);
            As2[row][kp + 1] = make_float2(v.y, v.y);
            As2[row][kp + 2] = make_float2(v.z, v.z);
            As2[row][kp + 3] = make_float2(v.w, v.w);
        }
        #pragma unroll
        for (int i = 0; i < 4; ++i) {
            int e = tid + i * 256;
            int kk = e >> 6;
            int n = e & 63;
            Bs[kk][n] = g_WpoT[(k0 + kk) * LL + bn + n];
        }
        __syncthreads();
        #pragma unroll
        for (int kk = 0; kk < 16; ++kk) {
            float2 b0 = *(const float2*)&Bs[kk][tx * 4];
            float2 b1 = *(const float2*)&Bs[kk][tx * 4 + 2];
            #pragma unroll
            for (int i = 0; i < 8; ++i) {
                float2 a2 = As2[ty * 8 + i][kk];
                ffma2(acc2[i][0], a2, b0);
                ffma2(acc2[i][1], a2, b1);
            }
        }
        __syncthreads();
    }
    float bp0 = b_post[bn + tx * 4], bp1 = b_post[bn + tx * 4 + 1];
    float bp2 = b_post[bn + tx * 4 + 2], bp3 = b_post[bn + tx * 4 + 3];
    #pragma unroll
    for (int i = 0; i < 8; ++i) {
        int m = bm + ty * 8 + i;
        float4 v;
        v.x = acc2[i][0].x + bp0; v.y = acc2[i][0].y + bp1;
        v.z = acc2[i][1].x + bp2; v.w = acc2[i][1].y + bp3;
        *(float4*)&outL[(size_t)m * LL + bn + tx * 4] = v;
    }
}

// ---------------- producer: obs-logits slices on the idle SMs ----------------
// slice t = obs[:, t, :] · WpoT + b_post  -> out logits base.  128b x 128n tiles,
// 512 threads, 8x4 f32x2 microtile, broadcast A reads.  Releases cnt[t] when done.
__device__ __forceinline__ void producer_body(int pc, int nprod,
        const float* __restrict__ obs, const float* __restrict__ b_post,
        float* __restrict__ outL, float* smem) {
    float2 (*As2)[130] = (float2(*)[130])smem;                   // [16 kk][130] dup {a,a}
    float  (*Bs)[128]  = (float(*)[128])(smem + 16 * 130 * 2);   // [16 kk][128]
    const int tid = threadIdx.x;
    const int ty = tid >> 5;          // 0..15 -> m = ty*8 (rows within b-block)
    const int tx = tid & 31;          // 0..31 -> n = tx*4
    const int arow = tid >> 2;        // 0..127
    const int akp  = (tid & 3) * 4;   // k quad within BK
    const int bkk  = tid >> 5;        // 0..15
    const int bn4  = (tid & 31) * 4;

    for (int t = 0; t < TT; ++t) {
        for (int tile = pc; tile < 32; tile += nprod) {
            const int bm = (tile & 3) * 128;    // b-block
            const int bn = (tile >> 2) * 128;   // n-block
            float2 acc[8][2];
            #pragma unroll
            for (int i = 0; i < 8; ++i) { acc[i][0] = make_float2(0.f, 0.f); acc[i][1] = make_float2(0.f, 0.f); }
            #pragma unroll 1
            for (int k0 = 0; k0 < HH; k0 += 16) {
                float4 va = *(const float4*)&obs[((size_t)(bm + arow) * TT + t) * HH + k0 + akp];
                As2[akp + 0][arow] = make_float2(va.x, va.x);
                As2[akp + 1][arow] = make_float2(va.y, va.y);
                As2[akp + 2][arow] = make_float2(va.z, va.z);
                As2[akp + 3][arow] = make_float2(va.w, va.w);
                float4 vb = *(const float4*)&g_WpoT[(size_t)(k0 + bkk) * LL + bn + bn4];
                *(float4*)&Bs[bkk][bn4] = vb;
                __syncthreads();
                #pragma unroll
                for (int kk = 0; kk < 16; ++kk) {
                    float4 b4 = *(const float4*)&Bs[kk][tx * 4];
                    float2 b0 = make_float2(b4.x, b4.y), b1 = make_float2(b4.z, b4.w);
                    float2 a[8];
                    *(float4*)&a[0] = *(const float4*)&As2[kk][ty * 8 + 0];  // rows +0,+1 (broadcast)
                    *(float4*)&a[2] = *(const float4*)&As2[kk][ty * 8 + 2];
                    *(float4*)&a[4] = *(const float4*)&As2[kk][ty * 8 + 4];
                    *(float4*)&a[6] = *(const float4*)&As2[kk][ty * 8 + 6];
                    #pragma unroll
                    for (int i = 0; i < 8; ++i) {
                        ffma2(acc[i][0], a[i], b0);
                        ffma2(acc[i][1], a[i], b1);
                    }
                }
                __syncthreads();
            }
            float4 bp = *(const float4*)&b_post[bn + tx * 4];
            #pragma unroll
            for (int i = 0; i < 8; ++i) {
                int b = bm + ty * 8 + i;
                float4 v;
                v.x = acc[i][0].x + bp.x; v.y = acc[i][0].y + bp.y;
                v.z = acc[i][1].x + bp.z; v.w = acc[i][1].y + bp.w;
                *(float4*)&outL[((size_t)b * TT + t) * LL + bn + tx * 4] = v;
            }
        }
        __threadfence();           // release slice-t stores (gpu scope)
        __syncthreads();           // all threads' stores ordered before the arrive
        if (tid == 0) atomicAdd(&g_cnt[t], 1);
    }
}

// ---------------- cluster-2 persistent scan + co-resident producer ----------------
#define OFF_GI     0
#define OFF_GH8    3072
#define OFF_GHR    9216
#define OFF_DET8   12288
#define OFF_DETOWN 16384
#define OFF_LG8    18432
#define OFF_LGR    26624
#define SMEM_FLOATS 30720

__global__ void __launch_bounds__(512, 1) __cluster_dims__(2, 1, 1)
scan_kernel(const float* __restrict__ action,
            const unsigned int* __restrict__ first,
            const float* __restrict__ gumbel,       // [T][B][1024]
            const float* __restrict__ b_hh,
            float* __restrict__ out,
            const float* __restrict__ obs,
            const float* __restrict__ b_post,
            int nprod) {

    extern __shared__ float smem[];

    // ---- producer CTAs (idle SMs) ----
    if (blockIdx.x >= NCTA) {
        int pc = (int)blockIdx.x - NCTA;
        if (pc < nprod)
            producer_body(pc, nprod, obs, b_post, out + LG_OFF, smem);
        return;
    }

    // ---- scan CTAs (round-9/11 proven body + slice-ready poll) ----
    float* s_gi     = smem + OFF_GI;
    float* s_gh8    = smem + OFF_GH8;
    float* s_ghr    = smem + OFF_GHR;
    float* s_det8   = smem + OFF_DET8;
    float* s_detown = smem + OFF_DETOWN;
    float* s_lg8    = smem + OFF_LG8;
    float* s_lgr    = smem + OFF_LGR;
    __shared__ int   s_idx[4][32];
    __shared__ float s_act[4][AA];
    __shared__ int   s_reset[8];     // pair-global rows, first[t]

    cg::cluster_group cluster = cg::this_cluster();
    const int rank = (int)cluster.block_rank();
    float* p_ghr  = (float*)cluster.map_shared_rank(s_ghr,  rank ^ 1);
    float* p_det8 = (float*)cluster.map_shared_rank(s_det8, rank ^ 1);
    float* p_lgr  = (float*)cluster.map_shared_rank(s_lgr,  rank ^ 1);

    const int tid = threadIdx.x;
    const int jh  = tid >> 8;        // intra-CTA jj-half
    const int lk  = tid & 255;
    const int pair  = blockIdx.x >> 1;
    const int prow0 = pair * 8;
    const int orow0 = prow0 + rank * 4;      // own rows base
    const int Jbase = rank * 128;            // this CTA's j slice
    int cur = 0;

    for (int t = 0; t < TT; ++t) {
        // ---- wait for obs-logits slice t (single-thread acquire; overlaps phase 1) ----
        if (tid == 0) {
            while (atomicAdd(&g_cnt[t], 0) < nprod) __nanosleep(64);
            __threadfence();
        }

        // ---- flags (all 8 rows) + action (own rows) ----
        if (tid < 8) {
            unsigned f = first[(prow0 + tid) * TT + t];
            s_reset[tid] = (t == 0) || (f != 0u);
        }
        if (tid >= 32 && tid < 32 + 4 * AA) {
            int e = tid - 32;
            s_act[e / AA][e % AA] = action[((size_t)(orow0 + e / AA) * TT + t) * AA + (e % AA)];
        }
        __syncthreads();

        // ---- zero carries on reset (det8 slice: all 8 rows; detown: own rows) ----
        #pragma unroll
        for (int k = 0; k < 2; ++k) {
            int idx = tid + k * 512;       // 1024 items: det8 slice
            int jj = idx >> 3, g = idx & 7;
            if (s_reset[g])
                *(float2*)&s_det8[cur * 2048 + jj * 16 + 2 * g] = make_float2(0.f, 0.f);
        }
        #pragma unroll
        for (int k = 0; k < 2; ++k) {
            int idx = tid + k * 512;       // 1024 items: detown
            int r = idx >> 8, u = idx & 255;
            if (s_reset[rank * 4 + r])
                s_detown[cur * 1024 + r * 256 + u] = 0.f;
        }
        __syncthreads();

        // ---- gi for own rows (bias + action + one-hot gather) ----
        for (int item = tid; item < 4 * 192; item += 512) {
            int r = item / 192;
            int q = (item % 192) * 4;
            float4 a4 = *(const float4*)&g_bc[q];
            #pragma unroll
            for (int j = 0; j < AA; ++j) {
                float av = s_act[r][j];
                float4 w = *(const float4*)&g_WcaT[j * KG + q];
                a4.x = fmaf(av, w.x, a4.x); a4.y = fmaf(av, w.y, a4.y);
                a4.z = fmaf(av, w.z, a4.z); a4.w = fmaf(av, w.w, a4.w);
            }
            if (!s_reset[rank * 4 + r]) {
                #pragma unroll 8
                for (int g = 0; g < 32; ++g) {
                    int c = (g << 5) + s_idx[r][g];
                    float4 w = *(const float4*)&g_WcT[c * KG + q];
                    a4.x += w.x; a4.y += w.y; a4.z += w.z; a4.w += w.w;
                }
            }
            *(float4*)&s_gi[r * KG + q] = a4;
        }

        // ---- phase 1: gh partial over my j-slice (8-deep weight prefetch) ----
        float2 gh[8][2];
        if (lk < 192) {
            const int q4 = lk * 4;
            if (rank == 0 && jh == 0) {
                float4 bh = *(const float4*)&b_hh[q4];
                #pragma unroll
                for (int g = 0; g < 8; ++g) {
                    gh[g][0] = make_float2(bh.x, bh.y);
                    gh[g][1] = make_float2(bh.z, bh.w);
                }
            } else {
                #pragma unroll
                for (int g = 0; g < 8; ++g) {
                    gh[g][0] = make_float2(0.f, 0.f);
                    gh[g][1] = make_float2(0.f, 0.f);
                }
            }
            const float4* wp  = (const float4*)&g_WhhT[(size_t)(Jbase + jh * 64) * KG + q4];
            const size_t  WS  = KG / 4;
            const float4* db4 = (const float4*)(s_det8 + cur * 2048 + (jh * 64) * 16);
            float4 wb8[8];
            #pragma unroll
            for (int p = 0; p < 8; ++p) wb8[p] = wp[(size_t)p * WS];
            #pragma unroll 1
            for (int base = 0; base < 64; base += 8) {
                #pragma unroll
                for (int p = 0; p < 8; ++p) {
                    float4 w = wb8[p];
                    int nj = base + 8 + p; nj = (nj < 64) ? nj : 63;
                    wb8[p] = wp[(size_t)nj * WS];
                    const float4* dq = db4 + (size_t)(base + p) * 4;
                    float4 dA = dq[0], dB = dq[1], dC = dq[2], dD = dq[3];
                    float2 wl = make_float2(w.x, w.y), wh2 = make_float2(w.z, w.w);
                    float2 dp[8] = { make_float2(dA.x, dA.y), make_float2(dA.z, dA.w),
                                     make_float2(dB.x, dB.y), make_float2(dB.z, dB.w),
                                     make_float2(dC.x, dC.y), make_float2(dC.z, dC.w),
                                     make_float2(dD.x, dD.y), make_float2(dD.z, dD.w) };
                    #pragma unroll
                    for (int g = 0; g < 8; ++g) {
                        ffma2(gh[g][0], dp[g], wl);
                        ffma2(gh[g][1], dp[g], wh2);
                    }
                }
            }
            if (jh == 0) {
                #pragma unroll
                for (int g = 0; g < 8; ++g)
                    *(float4*)&s_gh8[g * KG + q4] =
                        make_float4(gh[g][0].x, gh[g][0].y, gh[g][1].x, gh[g][1].y);
            }
        }
        __syncthreads();
        if (jh == 1 && lk < 192) {   // combine halves; push peer rows to peer's s_ghr
            const int q4 = lk * 4;
            const int pb = (rank ^ 1) * 4;
            #pragma unroll
            for (int g = 0; g < 8; ++g) {
                float4 p = *(const float4*)&s_gh8[g * KG + q4];
                float4 c = make_float4(p.x + gh[g][0].x, p.y + gh[g][0].y,
                                       p.z + gh[g][1].x, p.w + gh[g][1].y);
                *(float4*)&s_gh8[g * KG + q4] = c;
                if (g >= pb && g < pb + 4)
                    *(float4*)&p_ghr[(g - pb) * KG + q4] = c;
            }
        }
        cluster.sync();   // CS1: gh partials exchanged

        // ---- GRU for own rows + det distribution ----
        {
            const int u = lk;
            #pragma unroll
            for (int ii = 0; ii < 2; ++ii) {
                int i = jh * 2 + ii;          // own-local row
                int g = rank * 4 + i;         // pair-global row
                float ir = s_gi[i * KG + u];
                float hr = s_gh8[g * KG + u]       + s_ghr[i * KG + u];
                float iz = s_gi[i * KG + u + 256];
                float hz = s_gh8[g * KG + u + 256] + s_ghr[i * KG + u + 256];
                float in_ = s_gi[i * KG + u + 512];
                float hn = s_gh8[g * KG + u + 512] + s_ghr[i * KG + u + 512];
                float rg = 1.f / (1.f + expf(-(ir + hr)));
                float z  = 1.f / (1.f + expf(-(iz + hz)));
                float n  = tanhf(fmaf(rg, hn, in_));
                float dp = s_detown[cur * 1024 + i * 256 + u];
                float h  = (1.f - z) * n + z * dp;
                s_detown[(cur ^ 1) * 1024 + i * 256 + u] = h;
                float2 hh = make_float2(h, h);
                int jloc = u & 127;
                if ((u >> 7) == rank)
                    *(float2*)&s_det8[(cur ^ 1) * 2048 + jloc * 16 + 2 * g] = hh;
                else
                    *(float2*)&p_det8[(cur ^ 1) * 2048 + jloc * 16 + 2 * g] = hh;
                out[DET_OFF + ((size_t)(orow0 + i) * TT + t) * RR + u] = h;
            }
        }
        cluster.sync();   // CS2: new det slices exchanged

        // ---- phase 2: logits partial over my j-slice (8-deep weight prefetch) ----
        float2 acc[8][2];
        {
            const int q4 = lk * 4;
            #pragma unroll
            for (int g = 0; g < 8; ++g) {
                acc[g][0] = make_float2(0.f, 0.f);
                acc[g][1] = make_float2(0.f, 0.f);
            }
            const float4* wp  = (const float4*)&g_WphT[(size_t)(Jbase + jh * 64) * LL + q4];
            const size_t  WS  = LL / 4;
            const float4* db4 = (const float4*)(s_det8 + (cur ^ 1) * 2048 + (jh * 64) * 16);
            float4 wb8[8];
            #pragma unroll
            for (int p = 0; p < 8; ++p) wb8[p] = wp[(size_t)p * WS];
            #pragma unroll 1
            for (int base = 0; base < 64; base += 8) {
                #pragma unroll
                for (int p = 0; p < 8; ++p) {
                    float4 w = wb8[p];
                    int nj = base + 8 + p; nj = (nj < 64) ? nj : 63;
                    wb8[p] = wp[(size_t)nj * WS];
                    const float4* dq = db4 + (size_t)(base + p) * 4;
                    float4 dA = dq[0], dB = dq[1], dC = dq[2], dD = dq[3];
                    float2 wl = make_float2(w.x, w.y), wh2 = make_float2(w.z, w.w);
                    float2 dp[8] = { make_float2(dA.x, dA.y), make_float2(dA.z, dA.w),
                                     make_float2(dB.x, dB.y), make_float2(dB.z, dB.w),
                                     make_float2(dC.x, dC.y), make_float2(dC.z, dC.w),
                                     make_float2(dD.x, dD.y), make_float2(dD.z, dD.w) };
                    #pragma unroll
                    for (int g = 0; g < 8; ++g) {
                        ffma2(acc[g][0], dp[g], wl);
                        ffma2(acc[g][1], dp[g], wh2);
                    }
                }
            }
            if (jh == 0) {
                #pragma unroll
                for (int g = 0; g < 8; ++g)
                    *(float4*)&s_lg8[g * LL + q4] =
                        make_float4(acc[g][0].x, acc[g][0].y, acc[g][1].x, acc[g][1].y);
            }
        }
        __syncthreads();
        if (jh == 1) {
            const int q4 = lk * 4;
            const int pb = (rank ^ 1) * 4;
            #pragma unroll
            for (int g = 0; g < 8; ++g) {
                float4 p = *(const float4*)&s_lg8[g * LL + q4];
                float4 c = make_float4(p.x + acc[g][0].x, p.y + acc[g][0].y,
                                       p.z + acc[g][1].x, p.w + acc[g][1].y);
                *(float4*)&s_lg8[g * LL + q4] = c;
                if (g >= pb && g < pb + 4)
                    *(float4*)&p_lgr[(g - pb) * LL + q4] = c;
            }
        }
        cluster.sync();   // CS3: logits partials exchanged (also orders the slice-t acquire)

        // ---- finalize own rows: logits, gumbel argmax, one-hot stoch ----
        {
            const int q4 = lk * 4;
            #pragma unroll
            for (int ii = 0; ii < 2; ++ii) {
                int i = jh * 2 + ii;
                int g = rank * 4 + i;
                size_t bt = (size_t)(orow0 + i) * TT + t;
                float4 ob = *(const float4*)&out[LG_OFF + bt * LL + q4];  // obs part + b_post
                float4 pa = *(const float4*)&s_lg8[g * LL + q4];
                float4 pbv = *(const float4*)&s_lgr[i * LL + q4];
                float4 lg;
                lg.x = ob.x + pa.x + pbv.x; lg.y = ob.y + pa.y + pbv.y;
                lg.z = ob.z + pa.z + pbv.z; lg.w = ob.w + pa.w + pbv.w;
                *(float4*)&out[LG_OFF + bt * LL + q4] = lg;
                float4 g4 = *(const float4*)&gumbel[((size_t)t * BB + orow0 + i) * LL + q4];
                float v0 = lg.x + g4.x, v1 = lg.y + g4.y;
                float v2 = lg.z + g4.z, v3 = lg.w + g4.w;
                float bv = v0; int bi = q4;
                if (v1 > bv) { bv = v1; bi = q4 + 1; }
                if (v2 > bv) { bv = v2; bi = q4 + 2; }
                if (v3 > bv) { bv = v3; bi = q4 + 3; }
                #pragma unroll
                for (int off = 1; off < 8; off <<= 1) {
                    float ov = __shfl_xor_sync(0xffffffffu, bv, off);
                    int   oi = __shfl_xor_sync(0xffffffffu, bi, off);
                    if (ov > bv || (ov == bv && oi < bi)) { bv = ov; bi = oi; }
                }
                float4 sv;
                sv.x = (q4 + 0 == bi) ? 1.f : 0.f;
                sv.y = (q4 + 1 == bi) ? 1.f : 0.f;
                sv.z = (q4 + 2 == bi) ? 1.f : 0.f;
                sv.w = (q4 + 3 == bi) ? 1.f : 0.f;
                *(float4*)&out[ST_OFF + bt * LL + q4] = sv;
                if ((lk & 7) == 0) s_idx[i][lk >> 3] = bi & 31;
            }
        }
        cur ^= 1;
    }
}

// ---------------- launcher ----------------
extern "C" void kernel_launch(void* const* d_in, const int* in_sizes, int n_in,
                              void* d_out, int out_size) {
    const float* obs          = (const float*)d_in[0];
    const float* action       = (const float*)d_in[1];
    const unsigned int* first = (const unsigned int*)d_in[2];
    const float* gumbel       = (const float*)d_in[3];
    const float* W_in         = (const float*)d_in[4];
    const float* b_in         = (const float*)d_in[5];
    const float* W_ih         = (const float*)d_in[6];
    const float* W_hh         = (const float*)d_in[7];
    const float* b_ih         = (const float*)d_in[8];
    const float* b_hh         = (const float*)d_in[9];
    const float* W_post       = (const float*)d_in[10];
    const float* b_post       = (const float*)d_in[11];
    float* out = (float*)d_out;
    (void)in_sizes; (void)n_in; (void)out_size;

    static int nprod_s = -1;
    static int* cnt_ptr = nullptr;
    if (nprod_s < 0) {
        int dev = 0, smc = 0;
        cudaGetDevice(&dev);
        cudaDeviceGetAttribute(&smc, cudaDevAttrMultiProcessorCount, dev);
        nprod_s = (smc - NCTA) & ~1;          // co-resident producer CTAs (even, 1 wave)
        if (nprod_s < 0) nprod_s = 0;
        cudaGetSymbolAddress((void**)&cnt_ptr, g_cnt);
        cudaFuncSetAttribute(scan_kernel, cudaFuncAttributeMaxDynamicSharedMemorySize,
                             SMEM_FLOATS * sizeof(float));
    }

    prep_fuse<<<dim3(KG / 64, 17), 256>>>(W_in, b_in, W_ih, b_ih);
    prep_transpose<<<dim3(32, 16, 2), 256>>>(W_hh, W_post);

    if (nprod_s >= 2) {
        cudaMemsetAsync(cnt_ptr, 0, TT * sizeof(int));
        scan_kernel<<<NCTA + nprod_s, 512, SMEM_FLOATS * sizeof(float)>>>(
            action, first, gumbel, b_hh, out, obs, b_post, nprod_s);
    } else {
        // fallback: no idle SMs — serialize obs GEMM, mark all slices ready
        cudaMemsetAsync(cnt_ptr, 0x01, TT * sizeof(int));   // counters = 0x01010101 >> any nprod
        dim3 ggrid(LL / 64, (BB * TT) / 128);
        obs_gemm<<<ggrid, 256>>>(obs, b_post, out + LG_OFF);
        scan_kernel<<<NCTA, 512, SMEM_FLOATS * sizeof(float)>>>(
            action, first, gumbel, b_hh, out, obs, b_post, 1);
    }
}

// round 16
// speedup vs baseline: 3.7262x; 3.7262x over previous
#include <cuda_runtime.h>
#include <cooperative_groups.h>
#include <cstdint>

namespace cg = cooperative_groups;

// ---------------- problem dims ----------------
#define BB 512
#define TT 64
#define HH 256     // hidden / obs dim
#define AA 6       // action dim
#define RR 256     // recurrent dim
#define KG 768     // 3*RR gate dim
#define LL 1024    // latent dim
#define NCTA 128   // CTAs (64 clusters of 2); each cluster owns 8 rows, each CTA owns 4

// output layout: [deter | stoch | logits]
#define DET_OFF 0
#define ST_OFF  (BB * TT * RR)
#define LG_OFF  (BB * TT * RR + BB * TT * LL)

// ---------------- device scratch ----------------
__device__ __align__(16) float g_WcT[LL * KG];     // [c][k] fused stoch weights
__device__ __align__(16) float g_WcaT[AA * KG];    // [j][k] fused action weights
__device__ __align__(16) float g_bc[KG];           // b_ih + W_ih @ b_in
__device__ __align__(16) float g_WhhT[RR * KG];    // [j][k]
__device__ __align__(16) float g_WphT[RR * LL];    // [j][l]
__device__ __align__(16) float g_WpoT[HH * LL];    // [k][n]

// ---------------- packed fp32 helpers (FFMA2 path) ----------------
__device__ __forceinline__ void ffma2(float2& d, const float2 a, const float2 b) {
    asm("fma.rn.f32x2 %0, %1, %2, %0;"
        : "+l"(reinterpret_cast<unsigned long long&>(d))
        : "l"(reinterpret_cast<const unsigned long long&>(a)),
          "l"(reinterpret_cast<const unsigned long long&>(b)));
}

// ---------------- prep 1: fused GEMM  C[c][k] = sum_h W_in[h][c] * W_ih[k][h] ----------------
// 64k x 32c tiles -> grid 12 x 33 = 396 CTAs (2.7/SM) for latency hiding.
__global__ void __launch_bounds__(256) prep_fuse(const float* __restrict__ W_in,
                                                 const float* __restrict__ b_in,
                                                 const float* __restrict__ W_ih,
                                                 const float* __restrict__ b_ih) {
    __shared__ float As[16][32 + 1];   // [kk][cc]
    __shared__ float Bs[16][64 + 1];   // [kk][kn]
    const int tid = threadIdx.x;
    const int bk = blockIdx.x * 64;
    const int bc = blockIdx.y * 32;
    const int tyc = tid >> 4;          // 0..15 -> c pair
    const int txk = tid & 15;          // 0..15 -> k quad

    float acc[2][4];
    #pragma unroll
    for (int i = 0; i < 2; ++i)
        #pragma unroll
        for (int j = 0; j < 4; ++j) acc[i][j] = 0.f;

    for (int k0 = 0; k0 < HH; k0 += 16) {
        // A tile: 16x32 = 512 floats, 2 per thread, coalesced along c
        #pragma unroll
        for (int i = 0; i < 2; ++i) {
            int e = tid + i * 256;
            int kk = e >> 5, cc = e & 31;
            int c = bc + cc;
            float v = 0.f;
            if (c < 1030)       v = W_in[(size_t)(k0 + kk) * 1030 + c];
            else if (c == 1030) v = b_in[k0 + kk];
            As[kk][cc] = v;
        }
        // B tile: Bs[kk][kn] = W_ih[(bk+kn)][k0+kk]
        #pragma unroll
        for (int i = 0; i < 4; ++i) {
            int e = tid + i * 256;
            int kn = e >> 4, kk = e & 15;
            Bs[kk][kn] = W_ih[(size_t)(bk + kn) * HH + k0 + kk];
        }
        __syncthreads();
        #pragma unroll
        for (int kk = 0; kk < 16; ++kk) {
            float a[2], b[4];
            a[0] = As[kk][tyc * 2 + 0];
            a[1] = As[kk][tyc * 2 + 1];
            #pragma unroll
            for (int j = 0; j < 4; ++j) b[j] = Bs[kk][txk * 4 + j];
            #pragma unroll
            for (int i = 0; i < 2; ++i)
                #pragma unroll
                for (int j = 0; j < 4; ++j)
                    acc[i][j] = fmaf(a[i], b[j], acc[i][j]);
        }
        __syncthreads();
    }
    #pragma unroll
    for (int i = 0; i < 2; ++i) {
        int c = bc + tyc * 2 + i;
        int k = bk + txk * 4;
        if (c < LL) {
            *(float4*)&g_WcT[(size_t)c * KG + k] =
                make_float4(acc[i][0], acc[i][1], acc[i][2], acc[i][3]);
        } else if (c < 1030) {
            *(float4*)&g_WcaT[(size_t)(c - LL) * KG + k] =
                make_float4(acc[i][0], acc[i][1], acc[i][2], acc[i][3]);
        } else if (c == 1030) {
            float4 bi = *(const float4*)&b_ih[k];
            g_bc[k + 0] = acc[i][0] + bi.x;
            g_bc[k + 1] = acc[i][1] + bi.y;
            g_bc[k + 2] = acc[i][2] + bi.z;
            g_bc[k + 3] = acc[i][3] + bi.w;
        }
    }
}

// ---------------- prep 2: tiled transposes ----------------
__global__ void __launch_bounds__(256) prep_transpose(const float* __restrict__ W_hh,
                                                      const float* __restrict__ W_post) {
    __shared__ float tile[32][33];
    const int tid = threadIdx.x;
    const int tx = tid & 31;
    const int ty0 = tid >> 5;
    const int z = blockIdx.z;
    const int row0 = blockIdx.x * 32;
    const int col0 = blockIdx.y * 32;

    if (z == 0) {
        if (blockIdx.x >= 24 || blockIdx.y >= 8) return;
        #pragma unroll
        for (int r = 0; r < 4; ++r) {
            int row = ty0 + r * 8;
            tile[row][tx] = W_hh[(size_t)(row0 + row) * RR + col0 + tx];
        }
        __syncthreads();
        #pragma unroll
        for (int r = 0; r < 4; ++r) {
            int row = ty0 + r * 8;
            g_WhhT[(size_t)(col0 + row) * KG + row0 + tx] = tile[tx][row];
        }
    } else {
        #pragma unroll
        for (int r = 0; r < 4; ++r) {
            int row = ty0 + r * 8;
            tile[row][tx] = W_post[(size_t)(row0 + row) * (RR + HH) + col0 + tx];
        }
        __syncthreads();
        #pragma unroll
        for (int r = 0; r < 4; ++r) {
            int row = ty0 + r * 8;
            int m = col0 + row;
            float v = tile[tx][row];
            if (m < RR) g_WphT[(size_t)m * LL + row0 + tx] = v;
            else        g_WpoT[(size_t)(m - RR) * LL + row0 + tx] = v;
        }
    }
}

// ---------------- obs GEMM (round-5 proven: 128x64, BK=16, f32x2) ----------------
__global__ void __launch_bounds__(256) obs_gemm(const float* __restrict__ obs,
                                                const float* __restrict__ b_post,
                                                float* __restrict__ outL) {
    __shared__ float2 As2[128][17];   // duplicated {a,a}
    __shared__ float  Bs[16][64];
    int tid = threadIdx.x;
    int bm = blockIdx.y * 128;
    int bn = blockIdx.x * 64;
    int ty = tid >> 4;
    int tx = tid & 15;
    float2 acc2[8][2];
    #pragma unroll
    for (int i = 0; i < 8; ++i) { acc2[i][0] = make_float2(0.f, 0.f); acc2[i][1] = make_float2(0.f, 0.f); }

    for (int k0 = 0; k0 < HH; k0 += 16) {
        #pragma unroll
        for (int i = 0; i < 2; ++i) {
            int f = tid + i * 256;
            int row = f >> 2;
            int kp = (f & 3) * 4;
            float4 v = *(const float4*)&obs[(size_t)(bm + row) * HH + k0 + kp];
            As2[row][kp + 0] = make_float2(v.x, v.x);
            As2[row][kp + 1] = make_float2(v.y, v.y);
            As2[row][kp + 2] = make_float2(v.z, v.z);
            As2[row][kp + 3] = make_float2(v.w, v.w);
        }
        #pragma unroll
        for (int i = 0; i < 4; ++i) {
            int e = tid + i * 256;
            int kk = e >> 6;
            int n = e & 63;
            Bs[kk][n] = g_WpoT[(k0 + kk) * LL + bn + n];
        }
        __syncthreads();
        #pragma unroll
        for (int kk = 0; kk < 16; ++kk) {
            float2 b0 = *(const float2*)&Bs[kk][tx * 4];
            float2 b1 = *(const float2*)&Bs[kk][tx * 4 + 2];
            #pragma unroll
            for (int i = 0; i < 8; ++i) {
                float2 a2 = As2[ty * 8 + i][kk];
                ffma2(acc2[i][0], a2, b0);
                ffma2(acc2[i][1], a2, b1);
            }
        }
        __syncthreads();
    }
    float bp0 = b_post[bn + tx * 4], bp1 = b_post[bn + tx * 4 + 1];
    float bp2 = b_post[bn + tx * 4 + 2], bp3 = b_post[bn + tx * 4 + 3];
    #pragma unroll
    for (int i = 0; i < 8; ++i) {
        int m = bm + ty * 8 + i;
        float4 v;
        v.x = acc2[i][0].x + bp0; v.y = acc2[i][0].y + bp1;
        v.z = acc2[i][1].x + bp2; v.w = acc2[i][1].y + bp3;
        *(float4*)&outL[(size_t)m * LL + bn + tx * 4] = v;
    }
}

// ---------------- cluster-2 persistent scan (round-9/11 proven version, verbatim) ----------------
#define OFF_GI     0
#define OFF_GH8    3072
#define OFF_GHR    9216
#define OFF_DET8   12288
#define OFF_DETOWN 16384
#define OFF_LG8    18432
#define OFF_LGR    26624
#define SMEM_FLOATS 30720

__global__ void __launch_bounds__(512, 1) __cluster_dims__(2, 1, 1)
scan_kernel(const float* __restrict__ action,
            const unsigned int* __restrict__ first,
            const float* __restrict__ gumbel,       // [T][B][1024]
            const float* __restrict__ b_hh,
            float* __restrict__ out) {

    extern __shared__ float smem[];
    float* s_gi     = smem + OFF_GI;
    float* s_gh8    = smem + OFF_GH8;
    float* s_ghr    = smem + OFF_GHR;
    float* s_det8   = smem + OFF_DET8;
    float* s_detown = smem + OFF_DETOWN;
    float* s_lg8    = smem + OFF_LG8;
    float* s_lgr    = smem + OFF_LGR;
    __shared__ int   s_idx[4][32];
    __shared__ float s_act[4][AA];
    __shared__ int   s_reset[8];     // pair-global rows, first[t]

    cg::cluster_group cluster = cg::this_cluster();
    const int rank = (int)cluster.block_rank();
    float* p_ghr  = (float*)cluster.map_shared_rank(s_ghr,  rank ^ 1);
    float* p_det8 = (float*)cluster.map_shared_rank(s_det8, rank ^ 1);
    float* p_lgr  = (float*)cluster.map_shared_rank(s_lgr,  rank ^ 1);

    const int tid = threadIdx.x;
    const int jh  = tid >> 8;        // intra-CTA jj-half
    const int lk  = tid & 255;
    const int pair  = blockIdx.x >> 1;
    const int prow0 = pair * 8;
    const int orow0 = prow0 + rank * 4;      // own rows base
    const int Jbase = rank * 128;            // this CTA's j slice
    int cur = 0;

    for (int t = 0; t < TT; ++t) {
        // ---- flags (all 8 rows) + action (own rows) ----
        if (tid < 8) {
            unsigned f = first[(prow0 + tid) * TT + t];
            s_reset[tid] = (t == 0) || (f != 0u);
        }
        if (tid >= 32 && tid < 32 + 4 * AA) {
            int e = tid - 32;
            s_act[e / AA][e % AA] = action[((size_t)(orow0 + e / AA) * TT + t) * AA + (e % AA)];
        }
        __syncthreads();

        // ---- zero carries on reset (det8 slice: all 8 rows; detown: own rows) ----
        #pragma unroll
        for (int k = 0; k < 2; ++k) {
            int idx = tid + k * 512;       // 1024 items: det8 slice
            int jj = idx >> 3, g = idx & 7;
            if (s_reset[g])
                *(float2*)&s_det8[cur * 2048 + jj * 16 + 2 * g] = make_float2(0.f, 0.f);
        }
        #pragma unroll
        for (int k = 0; k < 2; ++k) {
            int idx = tid + k * 512;       // 1024 items: detown
            int r = idx >> 8, u = idx & 255;
            if (s_reset[rank * 4 + r])
                s_detown[cur * 1024 + r * 256 + u] = 0.f;
        }
        __syncthreads();

        // ---- gi for own rows (bias + action + one-hot gather) ----
        for (int item = tid; item < 4 * 192; item += 512) {
            int r = item / 192;
            int q = (item % 192) * 4;
            float4 a4 = *(const float4*)&g_bc[q];
            #pragma unroll
            for (int j = 0; j < AA; ++j) {
                float av = s_act[r][j];
                float4 w = *(const float4*)&g_WcaT[j * KG + q];
                a4.x = fmaf(av, w.x, a4.x); a4.y = fmaf(av, w.y, a4.y);
                a4.z = fmaf(av, w.z, a4.z); a4.w = fmaf(av, w.w, a4.w);
            }
            if (!s_reset[rank * 4 + r]) {
                #pragma unroll 8
                for (int g = 0; g < 32; ++g) {
                    int c = (g << 5) + s_idx[r][g];
                    float4 w = *(const float4*)&g_WcT[c * KG + q];
                    a4.x += w.x; a4.y += w.y; a4.z += w.z; a4.w += w.w;
                }
            }
            *(float4*)&s_gi[r * KG + q] = a4;
        }

        // ---- phase 1: gh partial over my j-slice (8-deep weight prefetch) ----
        float2 gh[8][2];
        if (lk < 192) {
            const int q4 = lk * 4;
            if (rank == 0 && jh == 0) {
                float4 bh = *(const float4*)&b_hh[q4];
                #pragma unroll
                for (int g = 0; g < 8; ++g) {
                    gh[g][0] = make_float2(bh.x, bh.y);
                    gh[g][1] = make_float2(bh.z, bh.w);
                }
            } else {
                #pragma unroll
                for (int g = 0; g < 8; ++g) {
                    gh[g][0] = make_float2(0.f, 0.f);
                    gh[g][1] = make_float2(0.f, 0.f);
                }
            }
            const float4* wp  = (const float4*)&g_WhhT[(size_t)(Jbase + jh * 64) * KG + q4];
            const size_t  WS  = KG / 4;
            const float4* db4 = (const float4*)(s_det8 + cur * 2048 + (jh * 64) * 16);
            float4 wb8[8];
            #pragma unroll
            for (int p = 0; p < 8; ++p) wb8[p] = wp[(size_t)p * WS];
            #pragma unroll 1
            for (int base = 0; base < 64; base += 8) {
                #pragma unroll
                for (int p = 0; p < 8; ++p) {
                    float4 w = wb8[p];
                    int nj = base + 8 + p; nj = (nj < 64) ? nj : 63;
                    wb8[p] = wp[(size_t)nj * WS];
                    const float4* dq = db4 + (size_t)(base + p) * 4;
                    float4 dA = dq[0], dB = dq[1], dC = dq[2], dD = dq[3];
                    float2 wl = make_float2(w.x, w.y), wh2 = make_float2(w.z, w.w);
                    float2 dp[8] = { make_float2(dA.x, dA.y), make_float2(dA.z, dA.w),
                                     make_float2(dB.x, dB.y), make_float2(dB.z, dB.w),
                                     make_float2(dC.x, dC.y), make_float2(dC.z, dC.w),
                                     make_float2(dD.x, dD.y), make_float2(dD.z, dD.w) };
                    #pragma unroll
                    for (int g = 0; g < 8; ++g) {
                        ffma2(gh[g][0], dp[g], wl);
                        ffma2(gh[g][1], dp[g], wh2);
                    }
                }
            }
            if (jh == 0) {
                #pragma unroll
                for (int g = 0; g < 8; ++g)
                    *(float4*)&s_gh8[g * KG + q4] =
                        make_float4(gh[g][0].x, gh[g][0].y, gh[g][1].x, gh[g][1].y);
            }
        }
        __syncthreads();
        if (jh == 1 && lk < 192) {   // combine halves; push peer rows to peer's s_ghr
            const int q4 = lk * 4;
            const int pb = (rank ^ 1) * 4;
            #pragma unroll
            for (int g = 0; g < 8; ++g) {
                float4 p = *(const float4*)&s_gh8[g * KG + q4];
                float4 c = make_float4(p.x + gh[g][0].x, p.y + gh[g][0].y,
                                       p.z + gh[g][1].x, p.w + gh[g][1].y);
                *(float4*)&s_gh8[g * KG + q4] = c;
                if (g >= pb && g < pb + 4)
                    *(float4*)&p_ghr[(g - pb) * KG + q4] = c;
            }
        }
        cluster.sync();   // CS1: gh partials exchanged

        // ---- GRU for own rows + det distribution ----
        {
            const int u = lk;
            #pragma unroll
            for (int ii = 0; ii < 2; ++ii) {
                int i = jh * 2 + ii;          // own-local row
                int g = rank * 4 + i;         // pair-global row
                float ir = s_gi[i * KG + u];
                float hr = s_gh8[g * KG + u]       + s_ghr[i * KG + u];
                float iz = s_gi[i * KG + u + 256];
                float hz = s_gh8[g * KG + u + 256] + s_ghr[i * KG + u + 256];
                float in_ = s_gi[i * KG + u + 512];
                float hn = s_gh8[g * KG + u + 512] + s_ghr[i * KG + u + 512];
                float rg = 1.f / (1.f + expf(-(ir + hr)));
                float z  = 1.f / (1.f + expf(-(iz + hz)));
                float n  = tanhf(fmaf(rg, hn, in_));
                float dp = s_detown[cur * 1024 + i * 256 + u];
                float h  = (1.f - z) * n + z * dp;
                s_detown[(cur ^ 1) * 1024 + i * 256 + u] = h;
                float2 hh = make_float2(h, h);
                int jloc = u & 127;
                if ((u >> 7) == rank)
                    *(float2*)&s_det8[(cur ^ 1) * 2048 + jloc * 16 + 2 * g] = hh;
                else
                    *(float2*)&p_det8[(cur ^ 1) * 2048 + jloc * 16 + 2 * g] = hh;
                out[DET_OFF + ((size_t)(orow0 + i) * TT + t) * RR + u] = h;
            }
        }
        cluster.sync();   // CS2: new det slices exchanged

        // ---- phase 2: logits partial over my j-slice (8-deep weight prefetch) ----
        float2 acc[8][2];
        {
            const int q4 = lk * 4;
            #pragma unroll
            for (int g = 0; g < 8; ++g) {
                acc[g][0] = make_float2(0.f, 0.f);
                acc[g][1] = make_float2(0.f, 0.f);
            }
            const float4* wp  = (const float4*)&g_WphT[(size_t)(Jbase + jh * 64) * LL + q4];
            const size_t  WS  = LL / 4;
            const float4* db4 = (const float4*)(s_det8 + (cur ^ 1) * 2048 + (jh * 64) * 16);
            float4 wb8[8];
            #pragma unroll
            for (int p = 0; p < 8; ++p) wb8[p] = wp[(size_t)p * WS];
            #pragma unroll 1
            for (int base = 0; base < 64; base += 8) {
                #pragma unroll
                for (int p = 0; p < 8; ++p) {
                    float4 w = wb8[p];
                    int nj = base + 8 + p; nj = (nj < 64) ? nj : 63;
                    wb8[p] = wp[(size_t)nj * WS];
                    const float4* dq = db4 + (size_t)(base + p) * 4;
                    float4 dA = dq[0], dB = dq[1], dC = dq[2], dD = dq[3];
                    float2 wl = make_float2(w.x, w.y), wh2 = make_float2(w.z, w.w);
                    float2 dp[8] = { make_float2(dA.x, dA.y), make_float2(dA.z, dA.w),
                                     make_float2(dB.x, dB.y), make_float2(dB.z, dB.w),
                                     make_float2(dC.x, dC.y), make_float2(dC.z, dC.w),
                                     make_float2(dD.x, dD.y), make_float2(dD.z, dD.w) };
                    #pragma unroll
                    for (int g = 0; g < 8; ++g) {
                        ffma2(acc[g][0], dp[g], wl);
                        ffma2(acc[g][1], dp[g], wh2);
                    }
                }
            }
            if (jh == 0) {
                #pragma unroll
                for (int g = 0; g < 8; ++g)
                    *(float4*)&s_lg8[g * LL + q4] =
                        make_float4(acc[g][0].x, acc[g][0].y, acc[g][1].x, acc[g][1].y);
            }
        }
        __syncthreads();
        if (jh == 1) {
            const int q4 = lk * 4;
            const int pb = (rank ^ 1) * 4;
            #pragma unroll
            for (int g = 0; g < 8; ++g) {
                float4 p = *(const float4*)&s_lg8[g * LL + q4];
                float4 c = make_float4(p.x + acc[g][0].x, p.y + acc[g][0].y,
                                       p.z + acc[g][1].x, p.w + acc[g][1].y);
                *(float4*)&s_lg8[g * LL + q4] = c;
                if (g >= pb && g < pb + 4)
                    *(float4*)&p_lgr[(g - pb) * LL + q4] = c;
            }
        }
        cluster.sync();   // CS3: logits partials exchanged

        // ---- finalize own rows: logits, gumbel argmax, one-hot stoch ----
        {
            const int q4 = lk * 4;
            #pragma unroll
            for (int ii = 0; ii < 2; ++ii) {
                int i = jh * 2 + ii;
                int g = rank * 4 + i;
                size_t bt = (size_t)(orow0 + i) * TT + t;
                float4 ob = *(const float4*)&out[LG_OFF + bt * LL + q4];  // obs part + b_post
                float4 pa = *(const float4*)&s_lg8[g * LL + q4];
                float4 pbv = *(const float4*)&s_lgr[i * LL + q4];
                float4 lg;
                lg.x = ob.x + pa.x + pbv.x; lg.y = ob.y + pa.y + pbv.y;
                lg.z = ob.z + pa.z + pbv.z; lg.w = ob.w + pa.w + pbv.w;
                *(float4*)&out[LG_OFF + bt * LL + q4] = lg;
                float4 g4 = *(const float4*)&gumbel[((size_t)t * BB + orow0 + i) * LL + q4];
                float v0 = lg.x + g4.x, v1 = lg.y + g4.y;
                float v2 = lg.z + g4.z, v3 = lg.w + g4.w;
                float bv = v0; int bi = q4;
                if (v1 > bv) { bv = v1; bi = q4 + 1; }
                if (v2 > bv) { bv = v2; bi = q4 + 2; }
                if (v3 > bv) { bv = v3; bi = q4 + 3; }
                #pragma unroll
                for (int off = 1; off < 8; off <<= 1) {
                    float ov = __shfl_xor_sync(0xffffffffu, bv, off);
                    int   oi = __shfl_xor_sync(0xffffffffu, bi, off);
                    if (ov > bv || (ov == bv && oi < bi)) { bv = ov; bi = oi; }
                }
                float4 sv;
                sv.x = (q4 + 0 == bi) ? 1.f : 0.f;
                sv.y = (q4 + 1 == bi) ? 1.f : 0.f;
                sv.z = (q4 + 2 == bi) ? 1.f : 0.f;
                sv.w = (q4 + 3 == bi) ? 1.f : 0.f;
                *(float4*)&out[ST_OFF + bt * LL + q4] = sv;
                if ((lk & 7) == 0) s_idx[i][lk >> 3] = bi & 31;
            }
        }
        cur ^= 1;
    }
}

// ---------------- launcher ----------------
extern "C" void kernel_launch(void* const* d_in, const int* in_sizes, int n_in,
                              void* d_out, int out_size) {
    const float* obs          = (const float*)d_in[0];
    const float* action       = (const float*)d_in[1];
    const unsigned int* first = (const unsigned int*)d_in[2];
    const float* gumbel       = (const float*)d_in[3];
    const float* W_in         = (const float*)d_in[4];
    const float* b_in         = (const float*)d_in[5];
    const float* W_ih         = (const float*)d_in[6];
    const float* W_hh         = (const float*)d_in[7];
    const float* b_ih         = (const float*)d_in[8];
    const float* b_hh         = (const float*)d_in[9];
    const float* W_post       = (const float*)d_in[10];
    const float* b_post       = (const float*)d_in[11];
    float* out = (float*)d_out;
    (void)in_sizes; (void)n_in; (void)out_size;

    static int smem_set = 0;
    if (!smem_set) {
        cudaFuncSetAttribute(scan_kernel, cudaFuncAttributeMaxDynamicSharedMemorySize,
                             SMEM_FLOATS * sizeof(float));
        smem_set = 1;
    }

    prep_fuse<<<dim3(KG / 64, 33), 256>>>(W_in, b_in, W_ih, b_ih);
    prep_transpose<<<dim3(32, 16, 2), 256>>>(W_hh, W_post);
    dim3 ggrid(LL / 64, (BB * TT) / 128);
    obs_gemm<<<ggrid, 256>>>(obs, b_post, out + LG_OFF);
    scan_kernel<<<NCTA, 512, SMEM_FLOATS * sizeof(float)>>>(action, first, gumbel, b_hh, out);
}